// round 5
// baseline (speedup 1.0000x reference)
#include <cuda_runtime.h>
#include <math.h>
#include <stdint.h>

#define N_NODES 50000
#define E_EDGES 800000
#define IN_DIM 512
#define HID 256
#define OUTD 128

// ---------------- scratch (static device allocations are allowed) ------------
__device__ __align__(16) float g_q[(size_t)N_NODES * HID];
__device__ __align__(16) float g_k[(size_t)N_NODES * HID];
__device__ __align__(16) float g_v[(size_t)N_NODES * HID];
__device__ __align__(16) float g_s[(size_t)N_NODES * HID];
__device__ __align__(16) float g_h[(size_t)N_NODES * HID];
__device__ __align__(16) float g_esc[E_EDGES];
__device__ int   g_cnt[N_NODES + 1];
__device__ int   g_off[N_NODES + 1];
__device__ int   g_cur[N_NODES];
__device__ int   g_eid[E_EDGES];
__device__ double g_sums[2];

// Parameter pack for the fused 4-projection GEMM (passed by value).
struct GemmQuad {
    const float* W[4];
    const float* b[4];
    float*       C[4];
};

// ---------------- GEMM: C[N,DOUT] = A[N,DIN] @ W[DIN,DOUT] + bias ------------
// BM=128, BN=128, BK=8, 256 threads, 8x8 per-thread microtile.
// blockIdx.z in [0,4) selects which of the 4 projection matrices this block
// computes; all 4 read the same A tiles -> L2 reuse across z-slices.
template <int DIN, int DOUT>
__global__ __launch_bounds__(256) void gemm_bias4(
    const float* __restrict__ A, GemmQuad quad, int N)
{
    constexpr int BM = 128, BN = 128, BK = 8;
    __shared__ float As[BK][BM];
    __shared__ float Ws[BK][BN];

    const float* __restrict__ W    = quad.W[blockIdx.z];
    const float* __restrict__ bias = quad.b[blockIdx.z];
    float* __restrict__       C    = quad.C[blockIdx.z];

    const int tid = threadIdx.x;
    const int m0 = blockIdx.x * BM;
    const int n0 = blockIdx.y * BN;
    const int tm = tid >> 4;   // 0..15 -> rows tm*8 .. tm*8+7
    const int tn = tid & 15;   // 0..15 -> cols tn*8 .. tn*8+7

    // A-tile load indices: 128 rows x 8 cols = 256 float4, 1 per thread
    const int ar = tid >> 1;          // row in tile 0..127
    const int ac = (tid & 1) * 4;     // col 0 or 4
    // W-tile load indices: 8 rows x 128 cols = 256 float4, 1 per thread
    const int wr = tid >> 5;          // k-row 0..7
    const int wc = (tid & 31) * 4;    // col 0..124

    float acc[8][8];
#pragma unroll
    for (int i = 0; i < 8; i++)
#pragma unroll
        for (int j = 0; j < 8; j++) acc[i][j] = 0.f;

    for (int k0 = 0; k0 < DIN; k0 += BK) {
        {
            int row = m0 + ar;
            float4 av = make_float4(0.f, 0.f, 0.f, 0.f);
            if (row < N)
                av = *reinterpret_cast<const float4*>(A + (size_t)row * DIN + k0 + ac);
            As[ac + 0][ar] = av.x;
            As[ac + 1][ar] = av.y;
            As[ac + 2][ar] = av.z;
            As[ac + 3][ar] = av.w;
        }
        {
            float4 wv = *reinterpret_cast<const float4*>(
                W + (size_t)(k0 + wr) * DOUT + n0 + wc);
            *reinterpret_cast<float4*>(&Ws[wr][wc]) = wv;
        }
        __syncthreads();

#pragma unroll
        for (int k = 0; k < BK; k++) {
            float4 a0 = *reinterpret_cast<const float4*>(&As[k][tm * 8]);
            float4 a1 = *reinterpret_cast<const float4*>(&As[k][tm * 8 + 4]);
            float4 b0 = *reinterpret_cast<const float4*>(&Ws[k][tn * 8]);
            float4 b1 = *reinterpret_cast<const float4*>(&Ws[k][tn * 8 + 4]);
            float a[8] = {a0.x, a0.y, a0.z, a0.w, a1.x, a1.y, a1.z, a1.w};
            float b[8] = {b0.x, b0.y, b0.z, b0.w, b1.x, b1.y, b1.z, b1.w};
#pragma unroll
            for (int i = 0; i < 8; i++)
#pragma unroll
                for (int j = 0; j < 8; j++) acc[i][j] = fmaf(a[i], b[j], acc[i][j]);
        }
        __syncthreads();
    }

    float4 bb0 = *reinterpret_cast<const float4*>(&bias[n0 + tn * 8]);
    float4 bb1 = *reinterpret_cast<const float4*>(&bias[n0 + tn * 8 + 4]);
#pragma unroll
    for (int i = 0; i < 8; i++) {
        int row = m0 + tm * 8 + i;
        if (row < N) {
            float4 o0, o1;
            o0.x = acc[i][0] + bb0.x;
            o0.y = acc[i][1] + bb0.y;
            o0.z = acc[i][2] + bb0.z;
            o0.w = acc[i][3] + bb0.w;
            o1.x = acc[i][4] + bb1.x;
            o1.y = acc[i][5] + bb1.y;
            o1.z = acc[i][6] + bb1.z;
            o1.w = acc[i][7] + bb1.w;
            float* cp = C + (size_t)row * DOUT + n0 + tn * 8;
            *reinterpret_cast<float4*>(cp) = o0;
            *reinterpret_cast<float4*>(cp + 4) = o1;
        }
    }
}

// ---------------- CSR build ---------------------------------------------------
__global__ void count_kernel(const int* __restrict__ dst, int* __restrict__ cnt, int E)
{
    int i = blockIdx.x * blockDim.x + threadIdx.x;
    if (i < E) atomicAdd(&cnt[dst[i]], 1);
}

__global__ __launch_bounds__(1024) void scan_kernel(
    const int* __restrict__ cnt, int* __restrict__ off, int* __restrict__ cur, int n)
{
    __shared__ int sh[1024];
    __shared__ int sh_carry;
    if (threadIdx.x == 0) sh_carry = 0;
    __syncthreads();
    for (int base = 0; base < n; base += 1024) {
        int i = base + threadIdx.x;
        int v = (i < n) ? cnt[i] : 0;
        sh[threadIdx.x] = v;
        __syncthreads();
        for (int s = 1; s < 1024; s <<= 1) {
            int t = (threadIdx.x >= (unsigned)s) ? sh[threadIdx.x - s] : 0;
            __syncthreads();
            sh[threadIdx.x] += t;
            __syncthreads();
        }
        int excl = sh_carry + sh[threadIdx.x] - v;
        if (i < n) { off[i] = excl; cur[i] = excl; }
        __syncthreads();
        if (threadIdx.x == 0) sh_carry += sh[1023];
        __syncthreads();
    }
    if (threadIdx.x == 0) off[n] = sh_carry;
}

__global__ void scatter_kernel(const int* __restrict__ dst,
                               int* __restrict__ cur, int* __restrict__ eid, int E)
{
    int i = blockIdx.x * blockDim.x + threadIdx.x;
    if (i < E) {
        int p = atomicAdd(&cur[dst[i]], 1);
        eid[p] = i;
    }
}

// ---------------- edge scores: esc[e] = exp(q[dst].k[src] / sqrt(D)) ---------
template <int D>
__global__ void edge_score(const int* __restrict__ src,
                           const int* __restrict__ dst,
                           const float* __restrict__ q, const float* __restrict__ k,
                           float* __restrict__ esc, int E, float inv_sqrt_d)
{
    int warp = (blockIdx.x * blockDim.x + threadIdx.x) >> 5;
    int lane = threadIdx.x & 31;
    if (warp >= E) return;
    int s = src[warp];
    int t = dst[warp];
    const float4* qr = reinterpret_cast<const float4*>(q + (size_t)t * D);
    const float4* kr = reinterpret_cast<const float4*>(k + (size_t)s * D);
    float acc = 0.f;
#pragma unroll
    for (int c = 0; c < D / 128; c++) {
        float4 a = qr[lane + 32 * c];
        float4 b = kr[lane + 32 * c];
        acc = fmaf(a.x, b.x, acc);
        acc = fmaf(a.y, b.y, acc);
        acc = fmaf(a.z, b.z, acc);
        acc = fmaf(a.w, b.w, acc);
    }
#pragma unroll
    for (int o = 16; o; o >>= 1) acc += __shfl_xor_sync(0xffffffffu, acc, o);
    if (lane == 0) esc[warp] = expf(acc * inv_sqrt_d);
}

// ---------------- per-node aggregation: out = sum(alpha*v[src]) + skip -------
template <int D>
__global__ void aggregate(const int* __restrict__ src,
                          const int* __restrict__ off, const int* __restrict__ eid,
                          const float* __restrict__ esc, const float* __restrict__ v,
                          const float* __restrict__ skip, float* __restrict__ out, int N)
{
    int warp = (blockIdx.x * blockDim.x + threadIdx.x) >> 5;
    int lane = threadIdx.x & 31;
    if (warp >= N) return;
    int b = off[warp], e = off[warp + 1];
    constexpr int C = D / 32;
    float acc[C];
#pragma unroll
    for (int c = 0; c < C; c++) acc[c] = 0.f;
    float den = 0.f;
    for (int j = b; j < e; j++) {
        int ed = eid[j];
        int s = src[ed];
        float w = esc[ed];
        den += w;
        const float* vr = v + (size_t)s * D;
#pragma unroll
        for (int c = 0; c < C; c++) acc[c] = fmaf(w, vr[lane + 32 * c], acc[c]);
    }
    float inv = (den > 0.f) ? 1.f / den : 0.f;
    float* orow = out + (size_t)warp * D;
    const float* srow = skip + (size_t)warp * D;
#pragma unroll
    for (int c = 0; c < C; c++) orow[lane + 32 * c] = acc[c] * inv + srow[lane + 32 * c];
}

// ---------------- global stats (graph layer norm) ----------------------------
__global__ void stats_reduce(const float* __restrict__ h, size_t n, double* __restrict__ sums)
{
    float s = 0.f, ss = 0.f;
    for (size_t i = (size_t)blockIdx.x * blockDim.x + threadIdx.x; i < n;
         i += (size_t)gridDim.x * blockDim.x) {
        float x = h[i];
        s += x;
        ss = fmaf(x, x, ss);
    }
    double ds = s, dss = ss;
#pragma unroll
    for (int o = 16; o; o >>= 1) {
        ds += __shfl_xor_sync(0xffffffffu, ds, o);
        dss += __shfl_xor_sync(0xffffffffu, dss, o);
    }
    __shared__ double shs[8], shss[8];
    int lane = threadIdx.x & 31, w = threadIdx.x >> 5;
    if (lane == 0) { shs[w] = ds; shss[w] = dss; }
    __syncthreads();
    if (w == 0) {
        ds = (lane < (int)(blockDim.x >> 5)) ? shs[lane] : 0.0;
        dss = (lane < (int)(blockDim.x >> 5)) ? shss[lane] : 0.0;
#pragma unroll
        for (int o = 4; o; o >>= 1) {
            ds += __shfl_xor_sync(0xffffffffu, ds, o);
            dss += __shfl_xor_sync(0xffffffffu, dss, o);
        }
        if (lane == 0) {
            atomicAdd(&sums[0], ds);
            atomicAdd(&sums[1], dss);
        }
    }
}

// ---------------- normalize (+ optional ELU), in place, float4 --------------
__global__ void norm_act(float* __restrict__ h, const double* __restrict__ sums,
                         const float* __restrict__ g, const float* __restrict__ be,
                         size_t n4, int D, int do_elu)
{
    double n = (double)(n4 * 4);
    double mean = sums[0] / n;
    double var = sums[1] / n - mean * mean;
    if (var < 0.0) var = 0.0;
    float fm = (float)mean;
    float inv = (float)(1.0 / (sqrt(var) + 1e-5));
    float4* h4 = reinterpret_cast<float4*>(h);
    for (size_t i = (size_t)blockIdx.x * blockDim.x + threadIdx.x; i < n4;
         i += (size_t)gridDim.x * blockDim.x) {
        float4 hv = h4[i];
        int col = (int)((i << 2) % (size_t)D);
        float4 gv = *reinterpret_cast<const float4*>(&g[col]);
        float4 bv = *reinterpret_cast<const float4*>(&be[col]);
        hv.x = (hv.x - fm) * inv * gv.x + bv.x;
        hv.y = (hv.y - fm) * inv * gv.y + bv.y;
        hv.z = (hv.z - fm) * inv * gv.z + bv.z;
        hv.w = (hv.w - fm) * inv * gv.w + bv.w;
        if (do_elu) {
            hv.x = hv.x > 0.f ? hv.x : expm1f(hv.x);
            hv.y = hv.y > 0.f ? hv.y : expm1f(hv.y);
            hv.z = hv.z > 0.f ? hv.z : expm1f(hv.z);
            hv.w = hv.w > 0.f ? hv.w : expm1f(hv.w);
        }
        h4[i] = hv;
    }
}

// ---------------- host orchestration -----------------------------------------
extern "C" void kernel_launch(void* const* d_in, const int* in_sizes, int n_in,
                              void* d_out, int out_size)
{
    const float* x   = (const float*)d_in[0];
    const float* Wq1 = (const float*)d_in[1];
    const float* bq1 = (const float*)d_in[2];
    const float* Wk1 = (const float*)d_in[3];
    const float* bk1 = (const float*)d_in[4];
    const float* Wv1 = (const float*)d_in[5];
    const float* bv1 = (const float*)d_in[6];
    const float* Ws1 = (const float*)d_in[7];
    const float* bs1 = (const float*)d_in[8];
    const float* g1  = (const float*)d_in[9];
    const float* be1 = (const float*)d_in[10];
    const float* Wq2 = (const float*)d_in[11];
    const float* bq2 = (const float*)d_in[12];
    const float* Wk2 = (const float*)d_in[13];
    const float* bk2 = (const float*)d_in[14];
    const float* Wv2 = (const float*)d_in[15];
    const float* bv2 = (const float*)d_in[16];
    const float* Ws2 = (const float*)d_in[17];
    const float* bs2 = (const float*)d_in[18];
    const float* g2  = (const float*)d_in[19];
    const float* be2 = (const float*)d_in[20];
    // JAX without x64 delivers edge_index as int32 (harness types: f32/i32/bf16).
    const int* ei = (const int*)d_in[21];

    const int N = in_sizes[0] / IN_DIM;
    const int E = in_sizes[21] / 2;
    const int* src = ei;
    const int* dst = ei + E;

    float *q, *k, *v, *s, *h, *esc;
    int *cnt, *off, *cur, *eid;
    double* sums;
    cudaGetSymbolAddress((void**)&q, g_q);
    cudaGetSymbolAddress((void**)&k, g_k);
    cudaGetSymbolAddress((void**)&v, g_v);
    cudaGetSymbolAddress((void**)&s, g_s);
    cudaGetSymbolAddress((void**)&h, g_h);
    cudaGetSymbolAddress((void**)&esc, g_esc);
    cudaGetSymbolAddress((void**)&cnt, g_cnt);
    cudaGetSymbolAddress((void**)&off, g_off);
    cudaGetSymbolAddress((void**)&cur, g_cur);
    cudaGetSymbolAddress((void**)&eid, g_eid);
    cudaGetSymbolAddress((void**)&sums, g_sums);

    float* out = (float*)d_out;

    // ---- CSR build (shared by both layers) ----
    cudaMemsetAsync(cnt, 0, (N + 1) * sizeof(int));
    count_kernel<<<(E + 255) / 256, 256>>>(dst, cnt, E);
    scan_kernel<<<1, 1024>>>(cnt, off, cur, N);
    scatter_kernel<<<(E + 255) / 256, 256>>>(dst, cur, eid, E);

    // ---- layer 1: fused 4-projection GEMM ----
    {
        GemmQuad quad;
        quad.W[0] = Wq1; quad.W[1] = Wk1; quad.W[2] = Wv1; quad.W[3] = Ws1;
        quad.b[0] = bq1; quad.b[1] = bk1; quad.b[2] = bv1; quad.b[3] = bs1;
        quad.C[0] = q;   quad.C[1] = k;   quad.C[2] = v;   quad.C[3] = s;
        dim3 grid((N + 127) / 128, HID / 128, 4);
        gemm_bias4<IN_DIM, HID><<<grid, 256>>>(x, quad, N);
    }
    edge_score<HID><<<(E * 32 + 255) / 256, 256>>>(src, dst, q, k, esc, E,
                                                   1.0f / sqrtf((float)HID));
    aggregate<HID><<<(N * 32 + 255) / 256, 256>>>(src, off, eid, esc, v, s, h, N);
    cudaMemsetAsync(sums, 0, 2 * sizeof(double));
    stats_reduce<<<2048, 256>>>(h, (size_t)N * HID, sums);
    norm_act<<<2048, 256>>>(h, sums, g1, be1, (size_t)N * HID / 4, HID, 1);

    // ---- layer 2: fused 4-projection GEMM ----
    {
        GemmQuad quad;
        quad.W[0] = Wq2; quad.W[1] = Wk2; quad.W[2] = Wv2; quad.W[3] = Ws2;
        quad.b[0] = bq2; quad.b[1] = bk2; quad.b[2] = bv2; quad.b[3] = bs2;
        quad.C[0] = q;   quad.C[1] = k;   quad.C[2] = v;   quad.C[3] = s;
        dim3 grid((N + 127) / 128, OUTD / 128, 4);
        gemm_bias4<HID, OUTD><<<grid, 256>>>(h, quad, N);
    }
    edge_score<OUTD><<<(E * 32 + 255) / 256, 256>>>(src, dst, q, k, esc, E,
                                                    1.0f / sqrtf((float)OUTD));
    aggregate<OUTD><<<(N * 32 + 255) / 256, 256>>>(src, off, eid, esc, v, s, out, N);
    cudaMemsetAsync(sums, 0, 2 * sizeof(double));
    stats_reduce<<<2048, 256>>>(out, (size_t)N * OUTD, sums);
    norm_act<<<2048, 256>>>(out, sums, g2, be2, (size_t)N * OUTD / 4, OUTD, 0);
}

// round 12
// speedup vs baseline: 1.3187x; 1.3187x over previous
#include <cuda_runtime.h>
#include <cuda_bf16.h>
#include <math.h>
#include <stdint.h>

#define N_NODES 50000
#define E_EDGES 800000
#define IN_DIM 512
#define HID 256
#define OUTD 128

// ---------------- scratch ----------------------------------------------------
__device__ __align__(16) float g_q[(size_t)N_NODES * HID];
__device__ __align__(16) float g_k[(size_t)N_NODES * HID];
__device__ __align__(16) float g_v[(size_t)N_NODES * HID];
__device__ __align__(16) float g_s[(size_t)N_NODES * HID];
__device__ __align__(16) float g_h[(size_t)N_NODES * HID];
__device__ __align__(16) float g_esc[E_EDGES];
__device__ __align__(16) __nv_bfloat16 g_ah[(size_t)N_NODES * IN_DIM];
__device__ __align__(16) __nv_bfloat16 g_al[(size_t)N_NODES * IN_DIM];
__device__ __align__(16) __nv_bfloat16 g_wth[4][IN_DIM * HID];
__device__ __align__(16) __nv_bfloat16 g_wtl[4][IN_DIM * HID];
__device__ int   g_cnt[N_NODES + 1];
__device__ int   g_off[N_NODES + 1];
__device__ int   g_cur[N_NODES];
__device__ int   g_eid[E_EDGES];
__device__ double g_sums[2];

// ---------------- conversion kernels -----------------------------------------
__global__ void split_bf16_kernel(const float* __restrict__ A,
                                  __nv_bfloat16* __restrict__ hi,
                                  __nv_bfloat16* __restrict__ lo, size_t n)
{
    for (size_t i = (size_t)blockIdx.x * blockDim.x + threadIdx.x; i < n;
         i += (size_t)gridDim.x * blockDim.x) {
        float a = A[i];
        __nv_bfloat16 h = __float2bfloat16(a);
        hi[i] = h;
        lo[i] = __float2bfloat16(a - __bfloat162float(h));
    }
}

struct WQuad { const float* W[4]; __nv_bfloat16* th[4]; __nv_bfloat16* tl[4]; };

// W [din, dout] -> Wt hi/lo [dout, din] bf16
__global__ void trans_split_kernel(WQuad q, int din, int dout)
{
    const float* W = q.W[blockIdx.z];
    __nv_bfloat16* th = q.th[blockIdx.z];
    __nv_bfloat16* tl = q.tl[blockIdx.z];
    int total = din * dout;
    for (int i = blockIdx.x * blockDim.x + threadIdx.x; i < total;
         i += gridDim.x * blockDim.x) {
        int o = i / din, kk = i - o * din;
        float w = W[kk * dout + o];
        __nv_bfloat16 h = __float2bfloat16(w);
        th[i] = h;
        tl[i] = __float2bfloat16(w - __bfloat162float(h));
    }
}

// ---------------- HMMA split-bf16 GEMM ----------------------------------------
// C[N, DOUT] = A[N, DIN] @ W[DIN, DOUT] + bias, via mma.sync m16n8k16 bf16.
// A = Ah + Al, Wt = Wh + Wl (bf16, [DOUT, DIN] k-contiguous).
// C ~= Ah Wh + Ah Wl + Al Wh (AlWl dropped, ~2^-18 relative).
// Block: 128x64 tile, 256 thr (8 warps = 4m x 2n), warp tile 32x32, BK=32.
struct BQuad {
    const __nv_bfloat16* Wh[4];
    const __nv_bfloat16* Wl[4];
    const float* b[4];
    float* C[4];
};

__device__ __forceinline__ void mma16816(float* d, const uint32_t* a, const uint32_t* b)
{
    asm volatile(
        "mma.sync.aligned.m16n8k16.row.col.f32.bf16.bf16.f32 "
        "{%0,%1,%2,%3}, {%4,%5,%6,%7}, {%8,%9}, {%0,%1,%2,%3};"
        : "+f"(d[0]), "+f"(d[1]), "+f"(d[2]), "+f"(d[3])
        : "r"(a[0]), "r"(a[1]), "r"(a[2]), "r"(a[3]), "r"(b[0]), "r"(b[1]));
}

template <int DIN, int DOUT>
__global__ __launch_bounds__(256) void mma_gemm(
    const __nv_bfloat16* __restrict__ Ah, const __nv_bfloat16* __restrict__ Al,
    BQuad quad, int N)
{
    constexpr int BM = 128, BN = 64, BK = 32;
    constexpr int AST = 40;  // smem row stride (bf16) — conflict-free frag loads
    __shared__ __nv_bfloat16 sAh[BM * AST];
    __shared__ __nv_bfloat16 sAl[BM * AST];
    __shared__ __nv_bfloat16 sBh[BN * AST];
    __shared__ __nv_bfloat16 sBl[BN * AST];

    const __nv_bfloat16* __restrict__ Wh = quad.Wh[blockIdx.z];
    const __nv_bfloat16* __restrict__ Wl = quad.Wl[blockIdx.z];
    const float* __restrict__ bias = quad.b[blockIdx.z];
    float* __restrict__ C = quad.C[blockIdx.z];

    const int tid = threadIdx.x;
    const int lane = tid & 31;
    const int wid = tid >> 5;
    const int warp_m = wid & 3;          // 4 m-strips of 32
    const int warp_n = wid >> 2;         // 2 n-strips of 32
    const int m0 = blockIdx.x * BM;
    const int n0 = blockIdx.y * BN;
    const int lr = lane >> 2;            // 0..7
    const int lc = (lane & 3) * 2;       // 0,2,4,6

    // A staging: 128 rows x 32 bf16 = 4 uint4/row; tid>>1 = row, tid&1 = half
    const int a_r = tid >> 1;
    const int a_half = (tid & 1) * 16;   // bf16 col offset 0 or 16
    // B staging: 64 rows x 4 uint4; tid>>2 = row, tid&3 = segment
    const int b_r = tid >> 2;
    const int b_seg = (tid & 3) * 8;

    float acc[2][4][4];
#pragma unroll
    for (int mt = 0; mt < 2; mt++)
#pragma unroll
        for (int nt = 0; nt < 4; nt++)
#pragma unroll
            for (int i = 0; i < 4; i++) acc[mt][nt][i] = 0.f;

    for (int kc = 0; kc < DIN / BK; kc++) {
        // ---- stage A (hi+lo) ----
        {
            int row = m0 + a_r;
            uint4 h0 = make_uint4(0, 0, 0, 0), h1 = h0, l0 = h0, l1 = h0;
            if (row < N) {
                size_t gi = (size_t)row * DIN + kc * BK + a_half;
                h0 = *reinterpret_cast<const uint4*>(Ah + gi);
                h1 = *reinterpret_cast<const uint4*>(Ah + gi + 8);
                l0 = *reinterpret_cast<const uint4*>(Al + gi);
                l1 = *reinterpret_cast<const uint4*>(Al + gi + 8);
            }
            *reinterpret_cast<uint4*>(&sAh[a_r * AST + a_half]) = h0;
            *reinterpret_cast<uint4*>(&sAh[a_r * AST + a_half + 8]) = h1;
            *reinterpret_cast<uint4*>(&sAl[a_r * AST + a_half]) = l0;
            *reinterpret_cast<uint4*>(&sAl[a_r * AST + a_half + 8]) = l1;
        }
        // ---- stage B (hi+lo) ----
        {
            size_t gi = (size_t)(n0 + b_r) * DIN + kc * BK + b_seg;
            *reinterpret_cast<uint4*>(&sBh[b_r * AST + b_seg]) =
                *reinterpret_cast<const uint4*>(Wh + gi);
            *reinterpret_cast<uint4*>(&sBl[b_r * AST + b_seg]) =
                *reinterpret_cast<const uint4*>(Wl + gi);
        }
        __syncthreads();

#pragma unroll
        for (int ks = 0; ks < 2; ks++) {
            const int kb = ks * 16;
            uint32_t ah[2][4], al[2][4], bh[4][2], bl[4][2];
#pragma unroll
            for (int mt = 0; mt < 2; mt++) {
                int r = warp_m * 32 + mt * 16 + lr;
                int c = kb + lc;
                ah[mt][0] = *reinterpret_cast<const uint32_t*>(&sAh[r * AST + c]);
                ah[mt][1] = *reinterpret_cast<const uint32_t*>(&sAh[(r + 8) * AST + c]);
                ah[mt][2] = *reinterpret_cast<const uint32_t*>(&sAh[r * AST + c + 8]);
                ah[mt][3] = *reinterpret_cast<const uint32_t*>(&sAh[(r + 8) * AST + c + 8]);
                al[mt][0] = *reinterpret_cast<const uint32_t*>(&sAl[r * AST + c]);
                al[mt][1] = *reinterpret_cast<const uint32_t*>(&sAl[(r + 8) * AST + c]);
                al[mt][2] = *reinterpret_cast<const uint32_t*>(&sAl[r * AST + c + 8]);
                al[mt][3] = *reinterpret_cast<const uint32_t*>(&sAl[(r + 8) * AST + c + 8]);
            }
#pragma unroll
            for (int nt = 0; nt < 4; nt++) {
                int n = warp_n * 32 + nt * 8 + lr;
                int c = kb + lc;
                bh[nt][0] = *reinterpret_cast<const uint32_t*>(&sBh[n * AST + c]);
                bh[nt][1] = *reinterpret_cast<const uint32_t*>(&sBh[n * AST + c + 8]);
                bl[nt][0] = *reinterpret_cast<const uint32_t*>(&sBl[n * AST + c]);
                bl[nt][1] = *reinterpret_cast<const uint32_t*>(&sBl[n * AST + c + 8]);
            }
#pragma unroll
            for (int mt = 0; mt < 2; mt++)
#pragma unroll
                for (int nt = 0; nt < 4; nt++) {
                    mma16816(acc[mt][nt], ah[mt], bh[nt]);
                    mma16816(acc[mt][nt], ah[mt], bl[nt]);
                    mma16816(acc[mt][nt], al[mt], bh[nt]);
                }
        }
        __syncthreads();
    }

    // ---- epilogue: acc + bias -> C ----
#pragma unroll
    for (int mt = 0; mt < 2; mt++) {
#pragma unroll
        for (int nt = 0; nt < 4; nt++) {
            int col = n0 + warp_n * 32 + nt * 8 + lc;
            float b0 = bias[col], b1 = bias[col + 1];
            int row0 = m0 + warp_m * 32 + mt * 16 + lr;
            if (row0 < N) {
                float2 o = make_float2(acc[mt][nt][0] + b0, acc[mt][nt][1] + b1);
                *reinterpret_cast<float2*>(C + (size_t)row0 * DOUT + col) = o;
            }
            int row1 = row0 + 8;
            if (row1 < N) {
                float2 o = make_float2(acc[mt][nt][2] + b0, acc[mt][nt][3] + b1);
                *reinterpret_cast<float2*>(C + (size_t)row1 * DOUT + col) = o;
            }
        }
    }
}

// ---------------- CSR build ---------------------------------------------------
__global__ void count_kernel(const int* __restrict__ dst, int* __restrict__ cnt, int E)
{
    int i = blockIdx.x * blockDim.x + threadIdx.x;
    if (i < E) atomicAdd(&cnt[dst[i]], 1);
}

__global__ __launch_bounds__(1024) void scan_kernel(
    const int* __restrict__ cnt, int* __restrict__ off, int* __restrict__ cur, int n)
{
    __shared__ int sh[1024];
    __shared__ int sh_carry;
    if (threadIdx.x == 0) sh_carry = 0;
    __syncthreads();
    for (int base = 0; base < n; base += 1024) {
        int i = base + threadIdx.x;
        int v = (i < n) ? cnt[i] : 0;
        sh[threadIdx.x] = v;
        __syncthreads();
        for (int s = 1; s < 1024; s <<= 1) {
            int t = (threadIdx.x >= (unsigned)s) ? sh[threadIdx.x - s] : 0;
            __syncthreads();
            sh[threadIdx.x] += t;
            __syncthreads();
        }
        int excl = sh_carry + sh[threadIdx.x] - v;
        if (i < n) { off[i] = excl; cur[i] = excl; }
        __syncthreads();
        if (threadIdx.x == 0) sh_carry += sh[1023];
        __syncthreads();
    }
    if (threadIdx.x == 0) off[n] = sh_carry;
}

__global__ void scatter_kernel(const int* __restrict__ dst,
                               int* __restrict__ cur, int* __restrict__ eid, int E)
{
    int i = blockIdx.x * blockDim.x + threadIdx.x;
    if (i < E) {
        int p = atomicAdd(&cur[dst[i]], 1);
        eid[p] = i;
    }
}

// ---------------- edge scores: esc[e] = exp(q[dst].k[src] / sqrt(D)) ---------
template <int D>
__global__ void edge_score(const int* __restrict__ src,
                           const int* __restrict__ dst,
                           const float* __restrict__ q, const float* __restrict__ k,
                           float* __restrict__ esc, int E, float inv_sqrt_d)
{
    int warp = (blockIdx.x * blockDim.x + threadIdx.x) >> 5;
    int lane = threadIdx.x & 31;
    if (warp >= E) return;
    int s = src[warp];
    int t = dst[warp];
    const float4* qr = reinterpret_cast<const float4*>(q + (size_t)t * D);
    const float4* kr = reinterpret_cast<const float4*>(k + (size_t)s * D);
    float acc = 0.f;
#pragma unroll
    for (int c = 0; c < D / 128; c++) {
        float4 a = qr[lane + 32 * c];
        float4 b = kr[lane + 32 * c];
        acc = fmaf(a.x, b.x, acc);
        acc = fmaf(a.y, b.y, acc);
        acc = fmaf(a.z, b.z, acc);
        acc = fmaf(a.w, b.w, acc);
    }
#pragma unroll
    for (int o = 16; o; o >>= 1) acc += __shfl_xor_sync(0xffffffffu, acc, o);
    if (lane == 0) esc[warp] = expf(acc * inv_sqrt_d);
}

// ---------------- per-node aggregation ----------------------------------------
template <int D>
__global__ void aggregate(const int* __restrict__ src,
                          const int* __restrict__ off, const int* __restrict__ eid,
                          const float* __restrict__ esc, const float* __restrict__ v,
                          const float* __restrict__ skip, float* __restrict__ out, int N)
{
    int warp = (blockIdx.x * blockDim.x + threadIdx.x) >> 5;
    int lane = threadIdx.x & 31;
    if (warp >= N) return;
    int b = off[warp], e = off[warp + 1];
    constexpr int C = D / 32;
    float acc[C];
#pragma unroll
    for (int c = 0; c < C; c++) acc[c] = 0.f;
    float den = 0.f;
    for (int j = b; j < e; j++) {
        int ed = eid[j];
        int s = src[ed];
        float w = esc[ed];
        den += w;
        const float* vr = v + (size_t)s * D;
#pragma unroll
        for (int c = 0; c < C; c++) acc[c] = fmaf(w, vr[lane + 32 * c], acc[c]);
    }
    float inv = (den > 0.f) ? 1.f / den : 0.f;
    float* orow = out + (size_t)warp * D;
    const float* srow = skip + (size_t)warp * D;
#pragma unroll
    for (int c = 0; c < C; c++) orow[lane + 32 * c] = acc[c] * inv + srow[lane + 32 * c];
}

// ---------------- global stats (graph layer norm) ----------------------------
__global__ void stats_reduce(const float* __restrict__ h, size_t n, double* __restrict__ sums)
{
    float s = 0.f, ss = 0.f;
    for (size_t i = (size_t)blockIdx.x * blockDim.x + threadIdx.x; i < n;
         i += (size_t)gridDim.x * blockDim.x) {
        float x = h[i];
        s += x;
        ss = fmaf(x, x, ss);
    }
    double ds = s, dss = ss;
#pragma unroll
    for (int o = 16; o; o >>= 1) {
        ds += __shfl_xor_sync(0xffffffffu, ds, o);
        dss += __shfl_xor_sync(0xffffffffu, dss, o);
    }
    __shared__ double shs[8], shss[8];
    int lane = threadIdx.x & 31, w = threadIdx.x >> 5;
    if (lane == 0) { shs[w] = ds; shss[w] = dss; }
    __syncthreads();
    if (w == 0) {
        ds = (lane < (int)(blockDim.x >> 5)) ? shs[lane] : 0.0;
        dss = (lane < (int)(blockDim.x >> 5)) ? shss[lane] : 0.0;
#pragma unroll
        for (int o = 4; o; o >>= 1) {
            ds += __shfl_xor_sync(0xffffffffu, ds, o);
            dss += __shfl_xor_sync(0xffffffffu, dss, o);
        }
        if (lane == 0) {
            atomicAdd(&sums[0], ds);
            atomicAdd(&sums[1], dss);
        }
    }
}

// ---------------- normalize (+ optional ELU), in place, float4 --------------
__global__ void norm_act(float* __restrict__ h, const double* __restrict__ sums,
                         const float* __restrict__ g, const float* __restrict__ be,
                         size_t n4, int D, int do_elu)
{
    double n = (double)(n4 * 4);
    double mean = sums[0] / n;
    double var = sums[1] / n - mean * mean;
    if (var < 0.0) var = 0.0;
    float fm = (float)mean;
    float inv = (float)(1.0 / (sqrt(var) + 1e-5));
    float4* h4 = reinterpret_cast<float4*>(h);
    for (size_t i = (size_t)blockIdx.x * blockDim.x + threadIdx.x; i < n4;
         i += (size_t)gridDim.x * blockDim.x) {
        float4 hv = h4[i];
        int col = (int)((i << 2) % (size_t)D);
        float4 gv = *reinterpret_cast<const float4*>(&g[col]);
        float4 bv = *reinterpret_cast<const float4*>(&be[col]);
        hv.x = (hv.x - fm) * inv * gv.x + bv.x;
        hv.y = (hv.y - fm) * inv * gv.y + bv.y;
        hv.z = (hv.z - fm) * inv * gv.z + bv.z;
        hv.w = (hv.w - fm) * inv * gv.w + bv.w;
        if (do_elu) {
            hv.x = hv.x > 0.f ? hv.x : expm1f(hv.x);
            hv.y = hv.y > 0.f ? hv.y : expm1f(hv.y);
            hv.z = hv.z > 0.f ? hv.z : expm1f(hv.z);
            hv.w = hv.w > 0.f ? hv.w : expm1f(hv.w);
        }
        h4[i] = hv;
    }
}

// ---------------- host orchestration -----------------------------------------
extern "C" void kernel_launch(void* const* d_in, const int* in_sizes, int n_in,
                              void* d_out, int out_size)
{
    const float* x   = (const float*)d_in[0];
    const float* Wq1 = (const float*)d_in[1];
    const float* bq1 = (const float*)d_in[2];
    const float* Wk1 = (const float*)d_in[3];
    const float* bk1 = (const float*)d_in[4];
    const float* Wv1 = (const float*)d_in[5];
    const float* bv1 = (const float*)d_in[6];
    const float* Ws1 = (const float*)d_in[7];
    const float* bs1 = (const float*)d_in[8];
    const float* g1  = (const float*)d_in[9];
    const float* be1 = (const float*)d_in[10];
    const float* Wq2 = (const float*)d_in[11];
    const float* bq2 = (const float*)d_in[12];
    const float* Wk2 = (const float*)d_in[13];
    const float* bk2 = (const float*)d_in[14];
    const float* Wv2 = (const float*)d_in[15];
    const float* bv2 = (const float*)d_in[16];
    const float* Ws2 = (const float*)d_in[17];
    const float* bs2 = (const float*)d_in[18];
    const float* g2  = (const float*)d_in[19];
    const float* be2 = (const float*)d_in[20];
    const int* ei = (const int*)d_in[21];   // JAX x32: edge_index arrives int32

    const int N = in_sizes[0] / IN_DIM;
    const int E = in_sizes[21] / 2;
    const int* src = ei;
    const int* dst = ei + E;

    float *q, *k, *v, *s, *h, *esc;
    __nv_bfloat16 *ah, *al, *wth, *wtl;
    int *cnt, *off, *cur, *eid;
    double* sums;
    cudaGetSymbolAddress((void**)&q, g_q);
    cudaGetSymbolAddress((void**)&k, g_k);
    cudaGetSymbolAddress((void**)&v, g_v);
    cudaGetSymbolAddress((void**)&s, g_s);
    cudaGetSymbolAddress((void**)&h, g_h);
    cudaGetSymbolAddress((void**)&esc, g_esc);
    cudaGetSymbolAddress((void**)&ah, g_ah);
    cudaGetSymbolAddress((void**)&al, g_al);
    cudaGetSymbolAddress((void**)&wth, g_wth);
    cudaGetSymbolAddress((void**)&wtl, g_wtl);
    cudaGetSymbolAddress((void**)&cnt, g_cnt);
    cudaGetSymbolAddress((void**)&off, g_off);
    cudaGetSymbolAddress((void**)&cur, g_cur);
    cudaGetSymbolAddress((void**)&eid, g_eid);
    cudaGetSymbolAddress((void**)&sums, g_sums);

    float* out = (float*)d_out;

    // ---- CSR build (shared by both layers) ----
    cudaMemsetAsync(cnt, 0, (N + 1) * sizeof(int));
    count_kernel<<<(E + 255) / 256, 256>>>(dst, cnt, E);
    scan_kernel<<<1, 1024>>>(cnt, off, cur, N);
    scatter_kernel<<<(E + 255) / 256, 256>>>(dst, cur, eid, E);

    // ---- layer 1 ----
    split_bf16_kernel<<<2048, 256>>>(x, ah, al, (size_t)N * IN_DIM);
    {
        WQuad wq;
        wq.W[0] = Wq1; wq.W[1] = Wk1; wq.W[2] = Wv1; wq.W[3] = Ws1;
        for (int i = 0; i < 4; i++) {
            wq.th[i] = wth + (size_t)i * (IN_DIM * HID);
            wq.tl[i] = wtl + (size_t)i * (IN_DIM * HID);
        }
        trans_split_kernel<<<dim3(128, 1, 4), 256>>>(wq, IN_DIM, HID);

        BQuad bq;
        for (int i = 0; i < 4; i++) {
            bq.Wh[i] = wq.th[i];
            bq.Wl[i] = wq.tl[i];
        }
        bq.b[0] = bq1; bq.b[1] = bk1; bq.b[2] = bv1; bq.b[3] = bs1;
        bq.C[0] = q;   bq.C[1] = k;   bq.C[2] = v;   bq.C[3] = s;
        dim3 grid((N + 127) / 128, HID / 64, 4);
        mma_gemm<IN_DIM, HID><<<grid, 256>>>(ah, al, bq, N);
    }
    edge_score<HID><<<(E * 32 + 255) / 256, 256>>>(src, dst, q, k, esc, E,
                                                   1.0f / sqrtf((float)HID));
    aggregate<HID><<<(N * 32 + 255) / 256, 256>>>(src, off, eid, esc, v, s, h, N);
    cudaMemsetAsync(sums, 0, 2 * sizeof(double));
    stats_reduce<<<2048, 256>>>(h, (size_t)N * HID, sums);
    norm_act<<<2048, 256>>>(h, sums, g1, be1, (size_t)N * HID / 4, HID, 1);

    // ---- layer 2 ----
    split_bf16_kernel<<<2048, 256>>>(h, ah, al, (size_t)N * HID);
    {
        WQuad wq;
        wq.W[0] = Wq2; wq.W[1] = Wk2; wq.W[2] = Wv2; wq.W[3] = Ws2;
        for (int i = 0; i < 4; i++) {
            wq.th[i] = wth + (size_t)i * (IN_DIM * HID);
            wq.tl[i] = wtl + (size_t)i * (IN_DIM * HID);
        }
        trans_split_kernel<<<dim3(64, 1, 4), 256>>>(wq, HID, OUTD);

        BQuad bq;
        for (int i = 0; i < 4; i++) {
            bq.Wh[i] = wq.th[i];
            bq.Wl[i] = wq.tl[i];
        }
        bq.b[0] = bq2; bq.b[1] = bk2; bq.b[2] = bv2; bq.b[3] = bs2;
        bq.C[0] = q;   bq.C[1] = k;   bq.C[2] = v;   bq.C[3] = s;
        dim3 grid((N + 127) / 128, OUTD / 64, 4);
        mma_gemm<HID, OUTD><<<grid, 256>>>(ah, al, bq, N);
    }
    edge_score<OUTD><<<(E * 32 + 255) / 256, 256>>>(src, dst, q, k, esc, E,
                                                    1.0f / sqrtf((float)OUTD));
    aggregate<OUTD><<<(N * 32 + 255) / 256, 256>>>(src, off, eid, esc, v, s, out, N);
    cudaMemsetAsync(sums, 0, 2 * sizeof(double));
    stats_reduce<<<2048, 256>>>(out, (size_t)N * OUTD, sums);
    norm_act<<<2048, 256>>>(out, sums, g2, be2, (size_t)N * OUTD / 4, OUTD, 0);
}

// round 13
// speedup vs baseline: 1.4102x; 1.0694x over previous
#include <cuda_runtime.h>
#include <cuda_bf16.h>
#include <math.h>
#include <stdint.h>

#define N_NODES 50000
#define E_EDGES 800000
#define IN_DIM 512
#define HID 256
#define OUTD 128

// ---------------- scratch ----------------------------------------------------
__device__ __align__(16) float g_q[(size_t)N_NODES * HID];
__device__ __align__(16) float g_k[(size_t)N_NODES * HID];
__device__ __align__(16) float g_v[(size_t)N_NODES * HID];
__device__ __align__(16) float g_s[(size_t)N_NODES * HID];
__device__ __align__(16) float g_h[(size_t)N_NODES * HID];
__device__ __align__(16) __nv_bfloat16 g_ah[(size_t)N_NODES * IN_DIM];
__device__ __align__(16) __nv_bfloat16 g_al[(size_t)N_NODES * IN_DIM];
__device__ __align__(16) __nv_bfloat16 g_wth[4][IN_DIM * HID];
__device__ __align__(16) __nv_bfloat16 g_wtl[4][IN_DIM * HID];
__device__ int   g_cnt[N_NODES + 1];
__device__ int   g_off[N_NODES + 1];
__device__ int   g_cur[N_NODES];
__device__ int   g_eid[E_EDGES];
__device__ double g_sums[2];

// ---------------- conversion kernels -----------------------------------------
__global__ void split_bf16_kernel(const float* __restrict__ A,
                                  __nv_bfloat16* __restrict__ hi,
                                  __nv_bfloat16* __restrict__ lo, size_t n)
{
    for (size_t i = (size_t)blockIdx.x * blockDim.x + threadIdx.x; i < n;
         i += (size_t)gridDim.x * blockDim.x) {
        float a = A[i];
        __nv_bfloat16 h = __float2bfloat16(a);
        hi[i] = h;
        lo[i] = __float2bfloat16(a - __bfloat162float(h));
    }
}

struct WQuad { const float* W[4]; __nv_bfloat16* th[4]; __nv_bfloat16* tl[4]; };

// W [din, dout] -> Wt hi/lo [dout, din] bf16
__global__ void trans_split_kernel(WQuad q, int din, int dout)
{
    const float* W = q.W[blockIdx.z];
    __nv_bfloat16* th = q.th[blockIdx.z];
    __nv_bfloat16* tl = q.tl[blockIdx.z];
    int total = din * dout;
    for (int i = blockIdx.x * blockDim.x + threadIdx.x; i < total;
         i += gridDim.x * blockDim.x) {
        int o = i / din, kk = i - o * din;
        float w = W[kk * dout + o];
        __nv_bfloat16 h = __float2bfloat16(w);
        th[i] = h;
        tl[i] = __float2bfloat16(w - __bfloat162float(h));
    }
}

// ---------------- HMMA split-bf16 GEMM (proven R12 design, unchanged) --------
struct BQuad {
    const __nv_bfloat16* Wh[4];
    const __nv_bfloat16* Wl[4];
    const float* b[4];
    float* C[4];
};

__device__ __forceinline__ void mma16816(float* d, const uint32_t* a, const uint32_t* b)
{
    asm volatile(
        "mma.sync.aligned.m16n8k16.row.col.f32.bf16.bf16.f32 "
        "{%0,%1,%2,%3}, {%4,%5,%6,%7}, {%8,%9}, {%0,%1,%2,%3};"
        : "+f"(d[0]), "+f"(d[1]), "+f"(d[2]), "+f"(d[3])
        : "r"(a[0]), "r"(a[1]), "r"(a[2]), "r"(a[3]), "r"(b[0]), "r"(b[1]));
}

template <int DIN, int DOUT>
__global__ __launch_bounds__(256) void mma_gemm(
    const __nv_bfloat16* __restrict__ Ah, const __nv_bfloat16* __restrict__ Al,
    BQuad quad, int N)
{
    constexpr int BM = 128, BN = 64, BK = 32;
    constexpr int AST = 40;
    __shared__ __nv_bfloat16 sAh[BM * AST];
    __shared__ __nv_bfloat16 sAl[BM * AST];
    __shared__ __nv_bfloat16 sBh[BN * AST];
    __shared__ __nv_bfloat16 sBl[BN * AST];

    const __nv_bfloat16* __restrict__ Wh = quad.Wh[blockIdx.z];
    const __nv_bfloat16* __restrict__ Wl = quad.Wl[blockIdx.z];
    const float* __restrict__ bias = quad.b[blockIdx.z];
    float* __restrict__ C = quad.C[blockIdx.z];

    const int tid = threadIdx.x;
    const int lane = tid & 31;
    const int wid = tid >> 5;
    const int warp_m = wid & 3;
    const int warp_n = wid >> 2;
    const int m0 = blockIdx.x * BM;
    const int n0 = blockIdx.y * BN;
    const int lr = lane >> 2;
    const int lc = (lane & 3) * 2;

    const int a_r = tid >> 1;
    const int a_half = (tid & 1) * 16;
    const int b_r = tid >> 2;
    const int b_seg = (tid & 3) * 8;

    float acc[2][4][4];
#pragma unroll
    for (int mt = 0; mt < 2; mt++)
#pragma unroll
        for (int nt = 0; nt < 4; nt++)
#pragma unroll
            for (int i = 0; i < 4; i++) acc[mt][nt][i] = 0.f;

    for (int kc = 0; kc < DIN / BK; kc++) {
        {
            int row = m0 + a_r;
            uint4 h0 = make_uint4(0, 0, 0, 0), h1 = h0, l0 = h0, l1 = h0;
            if (row < N) {
                size_t gi = (size_t)row * DIN + kc * BK + a_half;
                h0 = *reinterpret_cast<const uint4*>(Ah + gi);
                h1 = *reinterpret_cast<const uint4*>(Ah + gi + 8);
                l0 = *reinterpret_cast<const uint4*>(Al + gi);
                l1 = *reinterpret_cast<const uint4*>(Al + gi + 8);
            }
            *reinterpret_cast<uint4*>(&sAh[a_r * AST + a_half]) = h0;
            *reinterpret_cast<uint4*>(&sAh[a_r * AST + a_half + 8]) = h1;
            *reinterpret_cast<uint4*>(&sAl[a_r * AST + a_half]) = l0;
            *reinterpret_cast<uint4*>(&sAl[a_r * AST + a_half + 8]) = l1;
        }
        {
            size_t gi = (size_t)(n0 + b_r) * DIN + kc * BK + b_seg;
            *reinterpret_cast<uint4*>(&sBh[b_r * AST + b_seg]) =
                *reinterpret_cast<const uint4*>(Wh + gi);
            *reinterpret_cast<uint4*>(&sBl[b_r * AST + b_seg]) =
                *reinterpret_cast<const uint4*>(Wl + gi);
        }
        __syncthreads();

#pragma unroll
        for (int ks = 0; ks < 2; ks++) {
            const int kb = ks * 16;
            uint32_t ah[2][4], al[2][4], bh[4][2], bl[4][2];
#pragma unroll
            for (int mt = 0; mt < 2; mt++) {
                int r = warp_m * 32 + mt * 16 + lr;
                int c = kb + lc;
                ah[mt][0] = *reinterpret_cast<const uint32_t*>(&sAh[r * AST + c]);
                ah[mt][1] = *reinterpret_cast<const uint32_t*>(&sAh[(r + 8) * AST + c]);
                ah[mt][2] = *reinterpret_cast<const uint32_t*>(&sAh[r * AST + c + 8]);
                ah[mt][3] = *reinterpret_cast<const uint32_t*>(&sAh[(r + 8) * AST + c + 8]);
                al[mt][0] = *reinterpret_cast<const uint32_t*>(&sAl[r * AST + c]);
                al[mt][1] = *reinterpret_cast<const uint32_t*>(&sAl[(r + 8) * AST + c]);
                al[mt][2] = *reinterpret_cast<const uint32_t*>(&sAl[r * AST + c + 8]);
                al[mt][3] = *reinterpret_cast<const uint32_t*>(&sAl[(r + 8) * AST + c + 8]);
            }
#pragma unroll
            for (int nt = 0; nt < 4; nt++) {
                int n = warp_n * 32 + nt * 8 + lr;
                int c = kb + lc;
                bh[nt][0] = *reinterpret_cast<const uint32_t*>(&sBh[n * AST + c]);
                bh[nt][1] = *reinterpret_cast<const uint32_t*>(&sBh[n * AST + c + 8]);
                bl[nt][0] = *reinterpret_cast<const uint32_t*>(&sBl[n * AST + c]);
                bl[nt][1] = *reinterpret_cast<const uint32_t*>(&sBl[n * AST + c + 8]);
            }
#pragma unroll
            for (int mt = 0; mt < 2; mt++)
#pragma unroll
                for (int nt = 0; nt < 4; nt++) {
                    mma16816(acc[mt][nt], ah[mt], bh[nt]);
                    mma16816(acc[mt][nt], ah[mt], bl[nt]);
                    mma16816(acc[mt][nt], al[mt], bh[nt]);
                }
        }
        __syncthreads();
    }

#pragma unroll
    for (int mt = 0; mt < 2; mt++) {
#pragma unroll
        for (int nt = 0; nt < 4; nt++) {
            int col = n0 + warp_n * 32 + nt * 8 + lc;
            float b0 = bias[col], b1 = bias[col + 1];
            int row0 = m0 + warp_m * 32 + mt * 16 + lr;
            if (row0 < N) {
                float2 o = make_float2(acc[mt][nt][0] + b0, acc[mt][nt][1] + b1);
                *reinterpret_cast<float2*>(C + (size_t)row0 * DOUT + col) = o;
            }
            int row1 = row0 + 8;
            if (row1 < N) {
                float2 o = make_float2(acc[mt][nt][2] + b0, acc[mt][nt][3] + b1);
                *reinterpret_cast<float2*>(C + (size_t)row1 * DOUT + col) = o;
            }
        }
    }
}

// ---------------- CSR build ---------------------------------------------------
__global__ void count_kernel(const int* __restrict__ dst, int* __restrict__ cnt, int E)
{
    int i = blockIdx.x * blockDim.x + threadIdx.x;
    if (i < E) atomicAdd(&cnt[dst[i]], 1);
}

__global__ __launch_bounds__(1024) void scan_kernel(
    const int* __restrict__ cnt, int* __restrict__ off, int* __restrict__ cur, int n)
{
    __shared__ int sh[1024];
    __shared__ int sh_carry;
    if (threadIdx.x == 0) sh_carry = 0;
    __syncthreads();
    for (int base = 0; base < n; base += 1024) {
        int i = base + threadIdx.x;
        int v = (i < n) ? cnt[i] : 0;
        sh[threadIdx.x] = v;
        __syncthreads();
        for (int s = 1; s < 1024; s <<= 1) {
            int t = (threadIdx.x >= (unsigned)s) ? sh[threadIdx.x - s] : 0;
            __syncthreads();
            sh[threadIdx.x] += t;
            __syncthreads();
        }
        int excl = sh_carry + sh[threadIdx.x] - v;
        if (i < n) { off[i] = excl; cur[i] = excl; }
        __syncthreads();
        if (threadIdx.x == 0) sh_carry += sh[1023];
        __syncthreads();
    }
    if (threadIdx.x == 0) off[n] = sh_carry;
}

__global__ void scatter_kernel(const int* __restrict__ dst,
                               int* __restrict__ cur, int* __restrict__ eid, int E)
{
    int i = blockIdx.x * blockDim.x + threadIdx.x;
    if (i < E) {
        int p = atomicAdd(&cur[dst[i]], 1);
        eid[p] = i;
    }
}

// ---------------- fused attention: score + softmax + aggregate + skip --------
// warp per dst node; q row cached in registers; per edge: k row + v row.
template <int D>
__global__ __launch_bounds__(256) void fused_attn(
    const int* __restrict__ src,
    const int* __restrict__ off, const int* __restrict__ eid,
    const float* __restrict__ q, const float* __restrict__ k,
    const float* __restrict__ v, const float* __restrict__ skip,
    float* __restrict__ out, int N, float inv_sqrt_d)
{
    int warp = (blockIdx.x * blockDim.x + threadIdx.x) >> 5;
    int lane = threadIdx.x & 31;
    if (warp >= N) return;
    constexpr int C4 = D / 128;   // float4 chunks per lane

    float4 qr[C4];
    {
        const float4* qp = reinterpret_cast<const float4*>(q + (size_t)warp * D);
#pragma unroll
        for (int c = 0; c < C4; c++) qr[c] = qp[lane + 32 * c];
    }
    float4 acc[C4];
#pragma unroll
    for (int c = 0; c < C4; c++) acc[c] = make_float4(0.f, 0.f, 0.f, 0.f);
    float den = 0.f;

    const int b = off[warp], e = off[warp + 1];
#pragma unroll 2
    for (int j = b; j < e; j++) {
        int s = src[eid[j]];
        const float4* kr = reinterpret_cast<const float4*>(k + (size_t)s * D);
        const float4* vr = reinterpret_cast<const float4*>(v + (size_t)s * D);
        float4 kv[C4], vv[C4];
#pragma unroll
        for (int c = 0; c < C4; c++) {
            kv[c] = kr[lane + 32 * c];
            vv[c] = vr[lane + 32 * c];
        }
        float d0 = 0.f;
#pragma unroll
        for (int c = 0; c < C4; c++) {
            d0 = fmaf(qr[c].x, kv[c].x, d0);
            d0 = fmaf(qr[c].y, kv[c].y, d0);
            d0 = fmaf(qr[c].z, kv[c].z, d0);
            d0 = fmaf(qr[c].w, kv[c].w, d0);
        }
#pragma unroll
        for (int o = 16; o; o >>= 1) d0 += __shfl_xor_sync(0xffffffffu, d0, o);
        float w = expf(d0 * inv_sqrt_d);
        den += w;
#pragma unroll
        for (int c = 0; c < C4; c++) {
            acc[c].x = fmaf(w, vv[c].x, acc[c].x);
            acc[c].y = fmaf(w, vv[c].y, acc[c].y);
            acc[c].z = fmaf(w, vv[c].z, acc[c].z);
            acc[c].w = fmaf(w, vv[c].w, acc[c].w);
        }
    }

    float inv = (den > 0.f) ? 1.f / den : 0.f;
    const float4* sp = reinterpret_cast<const float4*>(skip + (size_t)warp * D);
    float4* op = reinterpret_cast<float4*>(out + (size_t)warp * D);
#pragma unroll
    for (int c = 0; c < C4; c++) {
        float4 sv = sp[lane + 32 * c];
        float4 o;
        o.x = acc[c].x * inv + sv.x;
        o.y = acc[c].y * inv + sv.y;
        o.z = acc[c].z * inv + sv.z;
        o.w = acc[c].w * inv + sv.w;
        op[lane + 32 * c] = o;
    }
}

// ---------------- global stats (graph layer norm) ----------------------------
__global__ void stats_reduce(const float* __restrict__ h, size_t n, double* __restrict__ sums)
{
    float s = 0.f, ss = 0.f;
    for (size_t i = (size_t)blockIdx.x * blockDim.x + threadIdx.x; i < n;
         i += (size_t)gridDim.x * blockDim.x) {
        float x = h[i];
        s += x;
        ss = fmaf(x, x, ss);
    }
    double ds = s, dss = ss;
#pragma unroll
    for (int o = 16; o; o >>= 1) {
        ds += __shfl_xor_sync(0xffffffffu, ds, o);
        dss += __shfl_xor_sync(0xffffffffu, dss, o);
    }
    __shared__ double shs[8], shss[8];
    int lane = threadIdx.x & 31, w = threadIdx.x >> 5;
    if (lane == 0) { shs[w] = ds; shss[w] = dss; }
    __syncthreads();
    if (w == 0) {
        ds = (lane < (int)(blockDim.x >> 5)) ? shs[lane] : 0.0;
        dss = (lane < (int)(blockDim.x >> 5)) ? shss[lane] : 0.0;
#pragma unroll
        for (int o = 4; o; o >>= 1) {
            ds += __shfl_xor_sync(0xffffffffu, ds, o);
            dss += __shfl_xor_sync(0xffffffffu, dss, o);
        }
        if (lane == 0) {
            atomicAdd(&sums[0], ds);
            atomicAdd(&sums[1], dss);
        }
    }
}

// ---------------- normalize + ELU -> split bf16 (layer1 -> layer2 input) -----
__global__ void norm_elu_split(const float* __restrict__ h, const double* __restrict__ sums,
                               const float* __restrict__ g, const float* __restrict__ be,
                               __nv_bfloat16* __restrict__ hi, __nv_bfloat16* __restrict__ lo,
                               size_t n, int D)
{
    double nn = (double)n;
    double mean = sums[0] / nn;
    double var = sums[1] / nn - mean * mean;
    if (var < 0.0) var = 0.0;
    float fm = (float)mean;
    float inv = (float)(1.0 / (sqrt(var) + 1e-5));
    for (size_t i = (size_t)blockIdx.x * blockDim.x + threadIdx.x; i < n;
         i += (size_t)gridDim.x * blockDim.x) {
        int col = (int)(i % (size_t)D);
        float y = (h[i] - fm) * inv * g[col] + be[col];
        y = y > 0.f ? y : expm1f(y);
        __nv_bfloat16 yh = __float2bfloat16(y);
        hi[i] = yh;
        lo[i] = __float2bfloat16(y - __bfloat162float(yh));
    }
}

// ---------------- normalize (final output, no elu), in place -----------------
__global__ void norm_act(float* __restrict__ h, const double* __restrict__ sums,
                         const float* __restrict__ g, const float* __restrict__ be,
                         size_t n4, int D)
{
    double n = (double)(n4 * 4);
    double mean = sums[0] / n;
    double var = sums[1] / n - mean * mean;
    if (var < 0.0) var = 0.0;
    float fm = (float)mean;
    float inv = (float)(1.0 / (sqrt(var) + 1e-5));
    float4* h4 = reinterpret_cast<float4*>(h);
    for (size_t i = (size_t)blockIdx.x * blockDim.x + threadIdx.x; i < n4;
         i += (size_t)gridDim.x * blockDim.x) {
        float4 hv = h4[i];
        int col = (int)((i << 2) % (size_t)D);
        float4 gv = *reinterpret_cast<const float4*>(&g[col]);
        float4 bv = *reinterpret_cast<const float4*>(&be[col]);
        hv.x = (hv.x - fm) * inv * gv.x + bv.x;
        hv.y = (hv.y - fm) * inv * gv.y + bv.y;
        hv.z = (hv.z - fm) * inv * gv.z + bv.z;
        hv.w = (hv.w - fm) * inv * gv.w + bv.w;
        h4[i] = hv;
    }
}

// ---------------- host orchestration -----------------------------------------
extern "C" void kernel_launch(void* const* d_in, const int* in_sizes, int n_in,
                              void* d_out, int out_size)
{
    const float* x   = (const float*)d_in[0];
    const float* Wq1 = (const float*)d_in[1];
    const float* bq1 = (const float*)d_in[2];
    const float* Wk1 = (const float*)d_in[3];
    const float* bk1 = (const float*)d_in[4];
    const float* Wv1 = (const float*)d_in[5];
    const float* bv1 = (const float*)d_in[6];
    const float* Ws1 = (const float*)d_in[7];
    const float* bs1 = (const float*)d_in[8];
    const float* g1  = (const float*)d_in[9];
    const float* be1 = (const float*)d_in[10];
    const float* Wq2 = (const float*)d_in[11];
    const float* bq2 = (const float*)d_in[12];
    const float* Wk2 = (const float*)d_in[13];
    const float* bk2 = (const float*)d_in[14];
    const float* Wv2 = (const float*)d_in[15];
    const float* bv2 = (const float*)d_in[16];
    const float* Ws2 = (const float*)d_in[17];
    const float* bs2 = (const float*)d_in[18];
    const float* g2  = (const float*)d_in[19];
    const float* be2 = (const float*)d_in[20];
    const int* ei = (const int*)d_in[21];   // JAX x32: edge_index arrives int32

    const int N = in_sizes[0] / IN_DIM;
    const int E = in_sizes[21] / 2;
    const int* src = ei;
    const int* dst = ei + E;

    float *q, *k, *v, *s, *h;
    __nv_bfloat16 *ah, *al, *wth, *wtl;
    int *cnt, *off, *cur, *eid;
    double* sums;
    cudaGetSymbolAddress((void**)&q, g_q);
    cudaGetSymbolAddress((void**)&k, g_k);
    cudaGetSymbolAddress((void**)&v, g_v);
    cudaGetSymbolAddress((void**)&s, g_s);
    cudaGetSymbolAddress((void**)&h, g_h);
    cudaGetSymbolAddress((void**)&ah, g_ah);
    cudaGetSymbolAddress((void**)&al, g_al);
    cudaGetSymbolAddress((void**)&wth, g_wth);
    cudaGetSymbolAddress((void**)&wtl, g_wtl);
    cudaGetSymbolAddress((void**)&cnt, g_cnt);
    cudaGetSymbolAddress((void**)&off, g_off);
    cudaGetSymbolAddress((void**)&cur, g_cur);
    cudaGetSymbolAddress((void**)&eid, g_eid);
    cudaGetSymbolAddress((void**)&sums, g_sums);

    float* out = (float*)d_out;

    // ---- CSR build (shared by both layers) ----
    cudaMemsetAsync(cnt, 0, (N + 1) * sizeof(int));
    count_kernel<<<(E + 255) / 256, 256>>>(dst, cnt, E);
    scan_kernel<<<1, 1024>>>(cnt, off, cur, N);
    scatter_kernel<<<(E + 255) / 256, 256>>>(dst, cur, eid, E);

    // ---- layer 1 ----
    split_bf16_kernel<<<2048, 256>>>(x, ah, al, (size_t)N * IN_DIM);
    {
        WQuad wq;
        wq.W[0] = Wq1; wq.W[1] = Wk1; wq.W[2] = Wv1; wq.W[3] = Ws1;
        for (int i = 0; i < 4; i++) {
            wq.th[i] = wth + (size_t)i * (IN_DIM * HID);
            wq.tl[i] = wtl + (size_t)i * (IN_DIM * HID);
        }
        trans_split_kernel<<<dim3(128, 1, 4), 256>>>(wq, IN_DIM, HID);

        BQuad bq;
        for (int i = 0; i < 4; i++) { bq.Wh[i] = wq.th[i]; bq.Wl[i] = wq.tl[i]; }
        bq.b[0] = bq1; bq.b[1] = bk1; bq.b[2] = bv1; bq.b[3] = bs1;
        bq.C[0] = q;   bq.C[1] = k;   bq.C[2] = v;   bq.C[3] = s;
        dim3 grid((N + 127) / 128, HID / 64, 4);
        mma_gemm<IN_DIM, HID><<<grid, 256>>>(ah, al, bq, N);
    }
    fused_attn<HID><<<(N * 32 + 255) / 256, 256>>>(src, off, eid, q, k, v, s, h, N,
                                                   1.0f / sqrtf((float)HID));
    cudaMemsetAsync(sums, 0, 2 * sizeof(double));
    stats_reduce<<<2048, 256>>>(h, (size_t)N * HID, sums);
    // normalize + ELU + bf16-split directly into layer-2 GEMM inputs
    norm_elu_split<<<2048, 256>>>(h, sums, g1, be1, ah, al, (size_t)N * HID, HID);

    // ---- layer 2 ----
    {
        WQuad wq;
        wq.W[0] = Wq2; wq.W[1] = Wk2; wq.W[2] = Wv2; wq.W[3] = Ws2;
        for (int i = 0; i < 4; i++) {
            wq.th[i] = wth + (size_t)i * (IN_DIM * HID);
            wq.tl[i] = wtl + (size_t)i * (IN_DIM * HID);
        }
        trans_split_kernel<<<dim3(64, 1, 4), 256>>>(wq, HID, OUTD);

        BQuad bq;
        for (int i = 0; i < 4; i++) { bq.Wh[i] = wq.th[i]; bq.Wl[i] = wq.tl[i]; }
        bq.b[0] = bq2; bq.b[1] = bk2; bq.b[2] = bv2; bq.b[3] = bs2;
        bq.C[0] = q;   bq.C[1] = k;   bq.C[2] = v;   bq.C[3] = s;
        dim3 grid((N + 127) / 128, OUTD / 64, 4);
        mma_gemm<HID, OUTD><<<grid, 256>>>(ah, al, bq, N);
    }
    fused_attn<OUTD><<<(N * 32 + 255) / 256, 256>>>(src, off, eid, q, k, v, s, out, N,
                                                    1.0f / sqrtf((float)OUTD));
    cudaMemsetAsync(sums, 0, 2 * sizeof(double));
    stats_reduce<<<2048, 256>>>(out, (size_t)N * OUTD, sums);
    norm_act<<<2048, 256>>>(out, sums, g2, be2, (size_t)N * OUTD / 4, OUTD);
}

// round 14
// speedup vs baseline: 1.4324x; 1.0157x over previous
#include <cuda_runtime.h>
#include <cuda_bf16.h>
#include <math.h>
#include <stdint.h>

#define N_NODES 50000
#define E_EDGES 800000
#define IN_DIM 512
#define HID 256
#define OUTD 128

// ---------------- scratch ----------------------------------------------------
__device__ __align__(16) float g_q[(size_t)N_NODES * HID];
__device__ __align__(16) float g_k[(size_t)N_NODES * HID];
__device__ __align__(16) float g_v[(size_t)N_NODES * HID];
__device__ __align__(16) float g_s[(size_t)N_NODES * HID];
__device__ __align__(16) float g_h[(size_t)N_NODES * HID];
__device__ __align__(16) __nv_bfloat16 g_ah[(size_t)N_NODES * IN_DIM];
__device__ __align__(16) __nv_bfloat16 g_al[(size_t)N_NODES * IN_DIM];
__device__ __align__(16) __nv_bfloat16 g_wth[4][IN_DIM * HID];
__device__ __align__(16) __nv_bfloat16 g_wtl[4][IN_DIM * HID];
__device__ int   g_cnt[N_NODES + 1];
__device__ int   g_off[N_NODES + 1];
__device__ int   g_cur[N_NODES];
__device__ int   g_eid[E_EDGES];
__device__ double g_sums[2];

// ---------------- conversion kernels (vectorized) -----------------------------
__device__ __forceinline__ uint32_t pack_bf16x2(__nv_bfloat16 a, __nv_bfloat16 b)
{
    __nv_bfloat162 p = __halves2bfloat162(a, b);
    return *reinterpret_cast<uint32_t*>(&p);
}

__global__ void split_bf16_kernel(const float4* __restrict__ A,
                                  uint2* __restrict__ hi,
                                  uint2* __restrict__ lo, size_t n4)
{
    for (size_t i = (size_t)blockIdx.x * blockDim.x + threadIdx.x; i < n4;
         i += (size_t)gridDim.x * blockDim.x) {
        float4 a = A[i];
        __nv_bfloat16 hx = __float2bfloat16(a.x), hy = __float2bfloat16(a.y);
        __nv_bfloat16 hz = __float2bfloat16(a.z), hw = __float2bfloat16(a.w);
        uint2 ho, lg;
        ho.x = pack_bf16x2(hx, hy);
        ho.y = pack_bf16x2(hz, hw);
        lg.x = pack_bf16x2(__float2bfloat16(a.x - __bfloat162float(hx)),
                           __float2bfloat16(a.y - __bfloat162float(hy)));
        lg.y = pack_bf16x2(__float2bfloat16(a.z - __bfloat162float(hz)),
                           __float2bfloat16(a.w - __bfloat162float(hw)));
        hi[i] = ho;
        lo[i] = lg;
    }
}

struct WQuad { const float* W[4]; __nv_bfloat16* th[4]; __nv_bfloat16* tl[4]; };

// W [din, dout] -> Wt hi/lo [dout, din] bf16
__global__ void trans_split_kernel(WQuad q, int din, int dout)
{
    const float* W = q.W[blockIdx.z];
    __nv_bfloat16* th = q.th[blockIdx.z];
    __nv_bfloat16* tl = q.tl[blockIdx.z];
    int total = din * dout;
    for (int i = blockIdx.x * blockDim.x + threadIdx.x; i < total;
         i += gridDim.x * blockDim.x) {
        int o = i / din, kk = i - o * din;
        float w = W[kk * dout + o];
        __nv_bfloat16 h = __float2bfloat16(w);
        th[i] = h;
        tl[i] = __float2bfloat16(w - __bfloat162float(h));
    }
}

// ---------------- HMMA split-bf16 GEMM (proven R12 design, unchanged) --------
struct BQuad {
    const __nv_bfloat16* Wh[4];
    const __nv_bfloat16* Wl[4];
    const float* b[4];
    float* C[4];
};

__device__ __forceinline__ void mma16816(float* d, const uint32_t* a, const uint32_t* b)
{
    asm volatile(
        "mma.sync.aligned.m16n8k16.row.col.f32.bf16.bf16.f32 "
        "{%0,%1,%2,%3}, {%4,%5,%6,%7}, {%8,%9}, {%0,%1,%2,%3};"
        : "+f"(d[0]), "+f"(d[1]), "+f"(d[2]), "+f"(d[3])
        : "r"(a[0]), "r"(a[1]), "r"(a[2]), "r"(a[3]), "r"(b[0]), "r"(b[1]));
}

template <int DIN, int DOUT>
__global__ __launch_bounds__(256) void mma_gemm(
    const __nv_bfloat16* __restrict__ Ah, const __nv_bfloat16* __restrict__ Al,
    BQuad quad, int N)
{
    constexpr int BM = 128, BN = 64, BK = 32;
    constexpr int AST = 40;
    __shared__ __nv_bfloat16 sAh[BM * AST];
    __shared__ __nv_bfloat16 sAl[BM * AST];
    __shared__ __nv_bfloat16 sBh[BN * AST];
    __shared__ __nv_bfloat16 sBl[BN * AST];

    const __nv_bfloat16* __restrict__ Wh = quad.Wh[blockIdx.z];
    const __nv_bfloat16* __restrict__ Wl = quad.Wl[blockIdx.z];
    const float* __restrict__ bias = quad.b[blockIdx.z];
    float* __restrict__ C = quad.C[blockIdx.z];

    const int tid = threadIdx.x;
    const int lane = tid & 31;
    const int wid = tid >> 5;
    const int warp_m = wid & 3;
    const int warp_n = wid >> 2;
    const int m0 = blockIdx.x * BM;
    const int n0 = blockIdx.y * BN;
    const int lr = lane >> 2;
    const int lc = (lane & 3) * 2;

    const int a_r = tid >> 1;
    const int a_half = (tid & 1) * 16;
    const int b_r = tid >> 2;
    const int b_seg = (tid & 3) * 8;

    float acc[2][4][4];
#pragma unroll
    for (int mt = 0; mt < 2; mt++)
#pragma unroll
        for (int nt = 0; nt < 4; nt++)
#pragma unroll
            for (int i = 0; i < 4; i++) acc[mt][nt][i] = 0.f;

    for (int kc = 0; kc < DIN / BK; kc++) {
        {
            int row = m0 + a_r;
            uint4 h0 = make_uint4(0, 0, 0, 0), h1 = h0, l0 = h0, l1 = h0;
            if (row < N) {
                size_t gi = (size_t)row * DIN + kc * BK + a_half;
                h0 = *reinterpret_cast<const uint4*>(Ah + gi);
                h1 = *reinterpret_cast<const uint4*>(Ah + gi + 8);
                l0 = *reinterpret_cast<const uint4*>(Al + gi);
                l1 = *reinterpret_cast<const uint4*>(Al + gi + 8);
            }
            *reinterpret_cast<uint4*>(&sAh[a_r * AST + a_half]) = h0;
            *reinterpret_cast<uint4*>(&sAh[a_r * AST + a_half + 8]) = h1;
            *reinterpret_cast<uint4*>(&sAl[a_r * AST + a_half]) = l0;
            *reinterpret_cast<uint4*>(&sAl[a_r * AST + a_half + 8]) = l1;
        }
        {
            size_t gi = (size_t)(n0 + b_r) * DIN + kc * BK + b_seg;
            *reinterpret_cast<uint4*>(&sBh[b_r * AST + b_seg]) =
                *reinterpret_cast<const uint4*>(Wh + gi);
            *reinterpret_cast<uint4*>(&sBl[b_r * AST + b_seg]) =
                *reinterpret_cast<const uint4*>(Wl + gi);
        }
        __syncthreads();

#pragma unroll
        for (int ks = 0; ks < 2; ks++) {
            const int kb = ks * 16;
            uint32_t ah[2][4], al[2][4], bh[4][2], bl[4][2];
#pragma unroll
            for (int mt = 0; mt < 2; mt++) {
                int r = warp_m * 32 + mt * 16 + lr;
                int c = kb + lc;
                ah[mt][0] = *reinterpret_cast<const uint32_t*>(&sAh[r * AST + c]);
                ah[mt][1] = *reinterpret_cast<const uint32_t*>(&sAh[(r + 8) * AST + c]);
                ah[mt][2] = *reinterpret_cast<const uint32_t*>(&sAh[r * AST + c + 8]);
                ah[mt][3] = *reinterpret_cast<const uint32_t*>(&sAh[(r + 8) * AST + c + 8]);
                al[mt][0] = *reinterpret_cast<const uint32_t*>(&sAl[r * AST + c]);
                al[mt][1] = *reinterpret_cast<const uint32_t*>(&sAl[(r + 8) * AST + c]);
                al[mt][2] = *reinterpret_cast<const uint32_t*>(&sAl[r * AST + c + 8]);
                al[mt][3] = *reinterpret_cast<const uint32_t*>(&sAl[(r + 8) * AST + c + 8]);
            }
#pragma unroll
            for (int nt = 0; nt < 4; nt++) {
                int n = warp_n * 32 + nt * 8 + lr;
                int c = kb + lc;
                bh[nt][0] = *reinterpret_cast<const uint32_t*>(&sBh[n * AST + c]);
                bh[nt][1] = *reinterpret_cast<const uint32_t*>(&sBh[n * AST + c + 8]);
                bl[nt][0] = *reinterpret_cast<const uint32_t*>(&sBl[n * AST + c]);
                bl[nt][1] = *reinterpret_cast<const uint32_t*>(&sBl[n * AST + c + 8]);
            }
#pragma unroll
            for (int mt = 0; mt < 2; mt++)
#pragma unroll
                for (int nt = 0; nt < 4; nt++) {
                    mma16816(acc[mt][nt], ah[mt], bh[nt]);
                    mma16816(acc[mt][nt], ah[mt], bl[nt]);
                    mma16816(acc[mt][nt], al[mt], bh[nt]);
                }
        }
        __syncthreads();
    }

#pragma unroll
    for (int mt = 0; mt < 2; mt++) {
#pragma unroll
        for (int nt = 0; nt < 4; nt++) {
            int col = n0 + warp_n * 32 + nt * 8 + lc;
            float b0 = bias[col], b1 = bias[col + 1];
            int row0 = m0 + warp_m * 32 + mt * 16 + lr;
            if (row0 < N) {
                float2 o = make_float2(acc[mt][nt][0] + b0, acc[mt][nt][1] + b1);
                *reinterpret_cast<float2*>(C + (size_t)row0 * DOUT + col) = o;
            }
            int row1 = row0 + 8;
            if (row1 < N) {
                float2 o = make_float2(acc[mt][nt][2] + b0, acc[mt][nt][3] + b1);
                *reinterpret_cast<float2*>(C + (size_t)row1 * DOUT + col) = o;
            }
        }
    }
}

// ---------------- CSR build ---------------------------------------------------
__global__ void count_kernel(const int* __restrict__ dst, int* __restrict__ cnt, int E)
{
    int i = blockIdx.x * blockDim.x + threadIdx.x;
    if (i < E) atomicAdd(&cnt[dst[i]], 1);
}

__global__ __launch_bounds__(1024) void scan_kernel(
    const int* __restrict__ cnt, int* __restrict__ off, int* __restrict__ cur, int n)
{
    __shared__ int sh[1024];
    __shared__ int sh_carry;
    if (threadIdx.x == 0) sh_carry = 0;
    __syncthreads();
    for (int base = 0; base < n; base += 1024) {
        int i = base + threadIdx.x;
        int v = (i < n) ? cnt[i] : 0;
        sh[threadIdx.x] = v;
        __syncthreads();
        for (int s = 1; s < 1024; s <<= 1) {
            int t = (threadIdx.x >= (unsigned)s) ? sh[threadIdx.x - s] : 0;
            __syncthreads();
            sh[threadIdx.x] += t;
            __syncthreads();
        }
        int excl = sh_carry + sh[threadIdx.x] - v;
        if (i < n) { off[i] = excl; cur[i] = excl; }
        __syncthreads();
        if (threadIdx.x == 0) sh_carry += sh[1023];
        __syncthreads();
    }
    if (threadIdx.x == 0) off[n] = sh_carry;
}

__global__ void scatter_kernel(const int* __restrict__ dst,
                               int* __restrict__ cur, int* __restrict__ eid, int E)
{
    int i = blockIdx.x * blockDim.x + threadIdx.x;
    if (i < E) {
        int p = atomicAdd(&cur[dst[i]], 1);
        eid[p] = i;
    }
}

// ---------------- fused attention: score+softmax+aggregate+skip+stats --------
// warp per dst node; q row in registers; 32 edge ids prefetched coalesced,
// broadcast by shfl -> inner loop has only row gathers (higher MLP).
template <int D>
__global__ __launch_bounds__(256) void fused_attn(
    const int* __restrict__ src,
    const int* __restrict__ off, const int* __restrict__ eid,
    const float* __restrict__ q, const float* __restrict__ k,
    const float* __restrict__ v, const float* __restrict__ skip,
    float* __restrict__ out, int N, float inv_sqrt_d, double* __restrict__ sums)
{
    int warp = (blockIdx.x * blockDim.x + threadIdx.x) >> 5;
    int lane = threadIdx.x & 31;
    if (warp >= N) return;
    constexpr int C4 = D / 128;   // float4 chunks per lane

    float4 qr[C4];
    {
        const float4* qp = reinterpret_cast<const float4*>(q + (size_t)warp * D);
#pragma unroll
        for (int c = 0; c < C4; c++) qr[c] = qp[lane + 32 * c];
    }
    float4 acc[C4];
#pragma unroll
    for (int c = 0; c < C4; c++) acc[c] = make_float4(0.f, 0.f, 0.f, 0.f);
    float den = 0.f;

    const int b = off[warp], e = off[warp + 1];
    for (int j0 = b; j0 < e; j0 += 32) {
        int myid = 0;
        if (j0 + lane < e) myid = src[eid[j0 + lane]];
        int cnt = min(32, e - j0);
#pragma unroll 2
        for (int t = 0; t < cnt; t++) {
            int s = __shfl_sync(0xffffffffu, myid, t);
            const float4* kr = reinterpret_cast<const float4*>(k + (size_t)s * D);
            const float4* vr = reinterpret_cast<const float4*>(v + (size_t)s * D);
            float4 kv[C4], vv[C4];
#pragma unroll
            for (int c = 0; c < C4; c++) {
                kv[c] = kr[lane + 32 * c];
                vv[c] = vr[lane + 32 * c];
            }
            float d0 = 0.f;
#pragma unroll
            for (int c = 0; c < C4; c++) {
                d0 = fmaf(qr[c].x, kv[c].x, d0);
                d0 = fmaf(qr[c].y, kv[c].y, d0);
                d0 = fmaf(qr[c].z, kv[c].z, d0);
                d0 = fmaf(qr[c].w, kv[c].w, d0);
            }
#pragma unroll
            for (int o = 16; o; o >>= 1) d0 += __shfl_xor_sync(0xffffffffu, d0, o);
            float w = expf(d0 * inv_sqrt_d);
            den += w;
#pragma unroll
            for (int c = 0; c < C4; c++) {
                acc[c].x = fmaf(w, vv[c].x, acc[c].x);
                acc[c].y = fmaf(w, vv[c].y, acc[c].y);
                acc[c].z = fmaf(w, vv[c].z, acc[c].z);
                acc[c].w = fmaf(w, vv[c].w, acc[c].w);
            }
        }
    }

    float inv = (den > 0.f) ? 1.f / den : 0.f;
    const float4* sp = reinterpret_cast<const float4*>(skip + (size_t)warp * D);
    float4* op = reinterpret_cast<float4*>(out + (size_t)warp * D);
    float ls = 0.f, lss = 0.f;
#pragma unroll
    for (int c = 0; c < C4; c++) {
        float4 sv = sp[lane + 32 * c];
        float4 o;
        o.x = acc[c].x * inv + sv.x;
        o.y = acc[c].y * inv + sv.y;
        o.z = acc[c].z * inv + sv.z;
        o.w = acc[c].w * inv + sv.w;
        op[lane + 32 * c] = o;
        ls += o.x + o.y + o.z + o.w;
        lss = fmaf(o.x, o.x, lss);
        lss = fmaf(o.y, o.y, lss);
        lss = fmaf(o.z, o.z, lss);
        lss = fmaf(o.w, o.w, lss);
    }
    // per-warp stats -> global sums (for graph layer norm)
#pragma unroll
    for (int o = 16; o; o >>= 1) {
        ls += __shfl_xor_sync(0xffffffffu, ls, o);
        lss += __shfl_xor_sync(0xffffffffu, lss, o);
    }
    if (lane == 0) {
        atomicAdd(&sums[0], (double)ls);
        atomicAdd(&sums[1], (double)lss);
    }
}

// ---------------- normalize + ELU -> split bf16 (vectorized) -----------------
__global__ void norm_elu_split(const float4* __restrict__ h, const double* __restrict__ sums,
                               const float* __restrict__ g, const float* __restrict__ be,
                               uint2* __restrict__ hi, uint2* __restrict__ lo,
                               size_t n4, int D)
{
    double nn = (double)(n4 * 4);
    double mean = sums[0] / nn;
    double var = sums[1] / nn - mean * mean;
    if (var < 0.0) var = 0.0;
    float fm = (float)mean;
    float inv = (float)(1.0 / (sqrt(var) + 1e-5));
    for (size_t i = (size_t)blockIdx.x * blockDim.x + threadIdx.x; i < n4;
         i += (size_t)gridDim.x * blockDim.x) {
        float4 hv = h[i];
        int col = (int)((i << 2) % (size_t)D);
        float4 gv = *reinterpret_cast<const float4*>(&g[col]);
        float4 bv = *reinterpret_cast<const float4*>(&be[col]);
        float yx = (hv.x - fm) * inv * gv.x + bv.x;
        float yy = (hv.y - fm) * inv * gv.y + bv.y;
        float yz = (hv.z - fm) * inv * gv.z + bv.z;
        float yw = (hv.w - fm) * inv * gv.w + bv.w;
        yx = yx > 0.f ? yx : expm1f(yx);
        yy = yy > 0.f ? yy : expm1f(yy);
        yz = yz > 0.f ? yz : expm1f(yz);
        yw = yw > 0.f ? yw : expm1f(yw);
        __nv_bfloat16 hx = __float2bfloat16(yx), hy = __float2bfloat16(yy);
        __nv_bfloat16 hz = __float2bfloat16(yz), hw = __float2bfloat16(yw);
        uint2 ho, lg;
        ho.x = pack_bf16x2(hx, hy);
        ho.y = pack_bf16x2(hz, hw);
        lg.x = pack_bf16x2(__float2bfloat16(yx - __bfloat162float(hx)),
                           __float2bfloat16(yy - __bfloat162float(hy)));
        lg.y = pack_bf16x2(__float2bfloat16(yz - __bfloat162float(hz)),
                           __float2bfloat16(yw - __bfloat162float(hw)));
        hi[i] = ho;
        lo[i] = lg;
    }
}

// ---------------- normalize (final output, no elu), in place -----------------
__global__ void norm_act(float* __restrict__ h, const double* __restrict__ sums,
                         const float* __restrict__ g, const float* __restrict__ be,
                         size_t n4, int D)
{
    double n = (double)(n4 * 4);
    double mean = sums[0] / n;
    double var = sums[1] / n - mean * mean;
    if (var < 0.0) var = 0.0;
    float fm = (float)mean;
    float inv = (float)(1.0 / (sqrt(var) + 1e-5));
    float4* h4 = reinterpret_cast<float4*>(h);
    for (size_t i = (size_t)blockIdx.x * blockDim.x + threadIdx.x; i < n4;
         i += (size_t)gridDim.x * blockDim.x) {
        float4 hv = h4[i];
        int col = (int)((i << 2) % (size_t)D);
        float4 gv = *reinterpret_cast<const float4*>(&g[col]);
        float4 bv = *reinterpret_cast<const float4*>(&be[col]);
        hv.x = (hv.x - fm) * inv * gv.x + bv.x;
        hv.y = (hv.y - fm) * inv * gv.y + bv.y;
        hv.z = (hv.z - fm) * inv * gv.z + bv.z;
        hv.w = (hv.w - fm) * inv * gv.w + bv.w;
        h4[i] = hv;
    }
}

// ---------------- host orchestration -----------------------------------------
extern "C" void kernel_launch(void* const* d_in, const int* in_sizes, int n_in,
                              void* d_out, int out_size)
{
    const float* x   = (const float*)d_in[0];
    const float* Wq1 = (const float*)d_in[1];
    const float* bq1 = (const float*)d_in[2];
    const float* Wk1 = (const float*)d_in[3];
    const float* bk1 = (const float*)d_in[4];
    const float* Wv1 = (const float*)d_in[5];
    const float* bv1 = (const float*)d_in[6];
    const float* Ws1 = (const float*)d_in[7];
    const float* bs1 = (const float*)d_in[8];
    const float* g1  = (const float*)d_in[9];
    const float* be1 = (const float*)d_in[10];
    const float* Wq2 = (const float*)d_in[11];
    const float* bq2 = (const float*)d_in[12];
    const float* Wk2 = (const float*)d_in[13];
    const float* bk2 = (const float*)d_in[14];
    const float* Wv2 = (const float*)d_in[15];
    const float* bv2 = (const float*)d_in[16];
    const float* Ws2 = (const float*)d_in[17];
    const float* bs2 = (const float*)d_in[18];
    const float* g2  = (const float*)d_in[19];
    const float* be2 = (const float*)d_in[20];
    const int* ei = (const int*)d_in[21];   // JAX x32: edge_index arrives int32

    const int N = in_sizes[0] / IN_DIM;
    const int E = in_sizes[21] / 2;
    const int* src = ei;
    const int* dst = ei + E;

    float *q, *k, *v, *s, *h;
    __nv_bfloat16 *ah, *al, *wth, *wtl;
    int *cnt, *off, *cur, *eid;
    double* sums;
    cudaGetSymbolAddress((void**)&q, g_q);
    cudaGetSymbolAddress((void**)&k, g_k);
    cudaGetSymbolAddress((void**)&v, g_v);
    cudaGetSymbolAddress((void**)&s, g_s);
    cudaGetSymbolAddress((void**)&h, g_h);
    cudaGetSymbolAddress((void**)&ah, g_ah);
    cudaGetSymbolAddress((void**)&al, g_al);
    cudaGetSymbolAddress((void**)&wth, g_wth);
    cudaGetSymbolAddress((void**)&wtl, g_wtl);
    cudaGetSymbolAddress((void**)&cnt, g_cnt);
    cudaGetSymbolAddress((void**)&off, g_off);
    cudaGetSymbolAddress((void**)&cur, g_cur);
    cudaGetSymbolAddress((void**)&eid, g_eid);
    cudaGetSymbolAddress((void**)&sums, g_sums);

    float* out = (float*)d_out;

    // ---- CSR build (shared by both layers) ----
    cudaMemsetAsync(cnt, 0, (N + 1) * sizeof(int));
    count_kernel<<<(E + 255) / 256, 256>>>(dst, cnt, E);
    scan_kernel<<<1, 1024>>>(cnt, off, cur, N);
    scatter_kernel<<<(E + 255) / 256, 256>>>(dst, cur, eid, E);

    // ---- layer 1 ----
    split_bf16_kernel<<<2048, 256>>>(reinterpret_cast<const float4*>(x),
                                     reinterpret_cast<uint2*>(ah),
                                     reinterpret_cast<uint2*>(al),
                                     (size_t)N * IN_DIM / 4);
    {
        WQuad wq;
        wq.W[0] = Wq1; wq.W[1] = Wk1; wq.W[2] = Wv1; wq.W[3] = Ws1;
        for (int i = 0; i < 4; i++) {
            wq.th[i] = wth + (size_t)i * (IN_DIM * HID);
            wq.tl[i] = wtl + (size_t)i * (IN_DIM * HID);
        }
        trans_split_kernel<<<dim3(128, 1, 4), 256>>>(wq, IN_DIM, HID);

        BQuad bq;
        for (int i = 0; i < 4; i++) { bq.Wh[i] = wq.th[i]; bq.Wl[i] = wq.tl[i]; }
        bq.b[0] = bq1; bq.b[1] = bk1; bq.b[2] = bv1; bq.b[3] = bs1;
        bq.C[0] = q;   bq.C[1] = k;   bq.C[2] = v;   bq.C[3] = s;
        dim3 grid((N + 127) / 128, HID / 64, 4);
        mma_gemm<IN_DIM, HID><<<grid, 256>>>(ah, al, bq, N);
    }
    cudaMemsetAsync(sums, 0, 2 * sizeof(double));
    fused_attn<HID><<<(N * 32 + 255) / 256, 256>>>(src, off, eid, q, k, v, s, h, N,
                                                   1.0f / sqrtf((float)HID), sums);
    norm_elu_split<<<2048, 256>>>(reinterpret_cast<const float4*>(h), sums, g1, be1,
                                  reinterpret_cast<uint2*>(ah),
                                  reinterpret_cast<uint2*>(al),
                                  (size_t)N * HID / 4, HID);

    // ---- layer 2 ----
    {
        WQuad wq;
        wq.W[0] = Wq2; wq.W[1] = Wk2; wq.W[2] = Wv2; wq.W[3] = Ws2;
        for (int i = 0; i < 4; i++) {
            wq.th[i] = wth + (size_t)i * (IN_DIM * HID);
            wq.tl[i] = wtl + (size_t)i * (IN_DIM * HID);
        }
        trans_split_kernel<<<dim3(64, 1, 4), 256>>>(wq, HID, OUTD);

        BQuad bq;
        for (int i = 0; i < 4; i++) { bq.Wh[i] = wq.th[i]; bq.Wl[i] = wq.tl[i]; }
        bq.b[0] = bq2; bq.b[1] = bk2; bq.b[2] = bv2; bq.b[3] = bs2;
        bq.C[0] = q;   bq.C[1] = k;   bq.C[2] = v;   bq.C[3] = s;
        dim3 grid((N + 127) / 128, OUTD / 64, 4);
        mma_gemm<HID, OUTD><<<grid, 256>>>(ah, al, bq, N);
    }
    cudaMemsetAsync(sums, 0, 2 * sizeof(double));
    fused_attn<OUTD><<<(N * 32 + 255) / 256, 256>>>(src, off, eid, q, k, v, s, out, N,
                                                    1.0f / sqrtf((float)OUTD), sums);
    norm_act<<<2048, 256>>>(out, sums, g2, be2, (size_t)N * OUTD / 4, OUTD);
}